// round 11
// baseline (speedup 1.0000x reference)
#include <cuda_runtime.h>
#include <cuda_bf16.h>

// Problem constants (fixed shapes for this dataset)
#define BATCH   16
#define FDIM    128
#define NMAX    10000
#define EMAX    320000
#define H1DIM   16
#define H2DIM   32
#define NCLS    10
#define BK      (BATCH * H2DIM)   // 512  (pooled vector)
#define CAP     128               // bucket capacity per node (Poisson(32) tail ~ e^-85)

// ---------------- device scratch (no allocations allowed) ----------------
// All zero at module load; every kernel_launch leaves them zeroed again
// (g_deg re-zeroed by k_l1, g_pool/g_done by k_l2's last block).
__device__ unsigned long long g_deg[NMAX];   // packed: cnt<<40 | fixed-point weighted deg
__device__ float g_dis[NMAX];            // rsqrt(deg)
__device__ float g_self[NMAX];           // dis*dis
__device__ int   g_cnt[NMAX];            // unpacked edge count
__device__ int2  g_edge[NMAX * CAP];     // bucketed CSR: (row, edge_weight bits)
__device__ float g_h[NMAX * BATCH];      // encoder out, layout [n][b]
__device__ float g_agg1[NMAX * BATCH];   // layer1 scalar aggregation, layout [n][b]
__device__ float g_pool[BK];             // pooled sums
__device__ int   g_done;                 // l2 completion counter

// ---------------- K1: ONE atomic per edge: degree accumulate + bucket placement ----------------
__global__ void k_deg(const int* __restrict__ ei, const float* __restrict__ ew, int E) {
    int e = blockIdx.x * blockDim.x + threadIdx.x;
    if (e >= E) return;
    int r = ei[e];
    int c = ei[E + e];
    float w = ew[e];
    unsigned long long inc = (1ull << 40)
        | (unsigned long long)__float2uint_rn(w * 16777216.0f);
    unsigned long long old = atomicAdd(&g_deg[c], inc);
    int slot = (int)(old >> 40);
    if (slot < CAP)
        g_edge[c * CAP + slot] = make_int2(r, __float_as_int(w));
}

// ---------------- K2: encoder + deg unpack.  h[n][b] = x[b,:]·enc_W[:,n] + enc_b[n] ----------------
__global__ void k_enc(const float* __restrict__ x, const float* __restrict__ encW,
                      const float* __restrict__ encb, int N) {
    __shared__ float sx[BATCH * FDIM];
    int tid = threadIdx.x;
    for (int i = tid; i < BATCH * FDIM; i += blockDim.x) sx[i] = x[i];
    __syncthreads();
    int n = blockIdx.x * blockDim.x + tid;
    if (n >= N) return;

    {   // unpack degree -> dis / self / cnt
        unsigned long long v = g_deg[n];
        int cnt = (int)(v >> 40);
        float deg = 1.0f + (float)(v & 0xFFFFFFFFFFull) * (1.0f / 16777216.0f);
        float d = rsqrtf(deg);
        g_dis[n] = d;
        g_self[n] = d * d;
        g_cnt[n] = cnt < CAP ? cnt : CAP;
    }

    float acc[BATCH];
    #pragma unroll
    for (int b = 0; b < BATCH; b++) acc[b] = 0.0f;
    #pragma unroll 16
    for (int f = 0; f < FDIM; f++) {
        float w = encW[(size_t)f * N + n];
        #pragma unroll
        for (int b = 0; b < BATCH; b++) acc[b] = fmaf(sx[b * FDIM + f], w, acc[b]);
    }
    float eb = encb[n];
    #pragma unroll
    for (int b = 0; b < BATCH; b++) g_h[n * BATCH + b] = acc[b] + eb;
}

// ---------------- K3: layer1 scalar aggregation (half-warp shfl, pipelined) ----------------
// 16 lanes per node; lane=b. Chunk i+1's edge+dis prefetched during chunk i's shfl/fma.
// Also re-zeroes g_deg for the next graph replay (its last reader, k_enc, already ran).
__global__ void k_l1(int N) {
    int tid = threadIdx.x;
    int lane = tid & 31;
    int b = lane & 15;
    unsigned hmask = 0xFFFFu << (lane & 16);     // this half-warp's mask
    int c = blockIdx.x * 16 + (tid >> 4);
    if (c >= N) return;

    float dc = g_dis[c];
    float agg  = g_self[c] * g_h[c * BATCH + b];
    float agg2 = 0.0f;
    int base = c * CAP;
    int cnt = g_cnt[c];

    bool valid = b < cnt;
    int2  ed = valid ? g_edge[base + b] : make_int2(0, 0);
    float dr = valid ? g_dis[ed.x] : 0.0f;

    for (int bs = 0; bs < cnt; bs += 16) {
        float nm = valid ? dr * __int_as_float(ed.y) * dc : 0.0f;
        int   rx = ed.x;
        // prefetch next chunk while shfl/fma below executes
        bool v2 = (bs + 16 + b) < cnt;
        int2  ed2 = v2 ? g_edge[base + bs + 16 + b] : make_int2(0, 0);
        float dr2 = v2 ? g_dis[ed2.x] : 0.0f;
        #pragma unroll
        for (int e = 0; e < 16; e += 2) {
            int   r0 = __shfl_sync(hmask, rx, e,     16);
            float n0 = __shfl_sync(hmask, nm, e,     16);
            int   r1 = __shfl_sync(hmask, rx, e + 1, 16);
            float n1 = __shfl_sync(hmask, nm, e + 1, 16);
            agg  = fmaf(n0, g_h[r0 * BATCH + b], agg);
            agg2 = fmaf(n1, g_h[r1 * BATCH + b], agg2);
        }
        ed = ed2; dr = dr2; valid = v2;
    }
    g_agg1[c * BATCH + b] = agg + agg2;
    if (b == 0) g_deg[c] = 0ull;                 // self-clean for next replay
}

// ---------------- K4: layer2 + fused head (last-block). ----------------
#define NPB 2
__global__ void k_l2(const float* __restrict__ W1, const float* __restrict__ b1,
                     const float* __restrict__ W2, const float* __restrict__ b2,
                     const float* __restrict__ c1W, const float* __restrict__ c1b,
                     const float* __restrict__ c2W, const float* __restrict__ c2b,
                     float* __restrict__ out, int N) {
    __shared__ float s_a[CAP * 16];        // staged agg1 rows of sources (8KB)
    __shared__ float s_norm[CAP];
    __shared__ int   s_row[CAP];
    __shared__ float sW2[H1DIM * H2DIM];
    __shared__ float sb2[H2DIM];
    int tid = threadIdx.x;                 // = b*16 + j
    int b = tid >> 4, j = tid & 15;
    unsigned hmask = 0xFFFFu << (tid & 16);
    float w1 = W1[j];
    float bb1 = b1[j];
    if (tid < H2DIM) sb2[tid] = b2[tid];
    for (int i = tid; i < H1DIM * H2DIM; i += 256) sW2[i] = W2[i];
    __syncthreads();

    float ps0 = 0.0f, ps1 = 0.0f;
    int c0 = blockIdx.x * NPB;
    for (int i = 0; i < NPB; i++) {
        int c = c0 + i;
        if (c >= N) break;                  // uniform across block
        int base = c * CAP;
        int m = g_cnt[c];                   // <= CAP: exactly one chunk
        float dcc = g_dis[c];
        float acc = g_self[c] * fmaxf(fmaf(g_agg1[c * BATCH + b], w1, bb1), 0.0f);

        if (tid < m) {
            int2 ed = g_edge[base + tid];
            s_row[tid]  = ed.x;
            s_norm[tid] = g_dis[ed.x] * __int_as_float(ed.y) * dcc;
        }
        __syncthreads();
        {
            int f = tid & 15, ei = tid >> 4;   // 16 edges per pass, 8 passes
            #pragma unroll
            for (int pass = 0; pass < 8; pass++) {
                int ep = ei + pass * 16;
                if (ep < m) {
                    int r = s_row[ep];                         // smem broadcast
                    s_a[ep * 16 + f] = g_agg1[r * BATCH + f];  // 64B coalesced
                }
            }
        }
        __syncthreads();
        {
            float a0 = 0.f, a1 = 0.f, a2 = 0.f, a3 = 0.f;
            int p = 0;
            for (; p + 4 <= m; p += 4) {
                a0 = fmaf(s_norm[p],     fmaxf(fmaf(s_a[(p)     * 16 + b], w1, bb1), 0.f), a0);
                a1 = fmaf(s_norm[p + 1], fmaxf(fmaf(s_a[(p + 1) * 16 + b], w1, bb1), 0.f), a1);
                a2 = fmaf(s_norm[p + 2], fmaxf(fmaf(s_a[(p + 2) * 16 + b], w1, bb1), 0.f), a2);
                a3 = fmaf(s_norm[p + 3], fmaxf(fmaf(s_a[(p + 3) * 16 + b], w1, bb1), 0.f), a3);
            }
            for (; p < m; p++)
                a0 = fmaf(s_norm[p], fmaxf(fmaf(s_a[p * 16 + b], w1, bb1), 0.f), a0);
            acc += (a0 + a1) + (a2 + a3);
        }
        // epilogue via half-warp shfl (threads b*16..b*16+15 are one half-warp)
        float v0 = sb2[j], v1 = sb2[j + 16];
        #pragma unroll
        for (int jj = 0; jj < H1DIM; jj++) {
            float a = __shfl_sync(hmask, acc, jj, 16);
            v0 = fmaf(a, sW2[jj * H2DIM + j],      v0);
            v1 = fmaf(a, sW2[jj * H2DIM + j + 16], v1);
        }
        ps0 += fmaxf(v0, 0.0f);
        ps1 += fmaxf(v1, 0.0f);
        __syncthreads();                    // staging arrays reused next node
    }
    atomicAdd(&g_pool[b * H2DIM + j],      ps0);
    atomicAdd(&g_pool[b * H2DIM + j + 16], ps1);

    // ---- fused classifier head: last block to finish runs it ----
    __threadfence();
    __shared__ int s_last;
    if (tid == 0) {
        int d = atomicAdd(&g_done, 1);
        s_last = (d == (int)gridDim.x - 1);
    }
    __syncthreads();
    if (!s_last) return;

    __shared__ float sp[BK];
    __shared__ float sz[BATCH * H1DIM];
    float invN = 1.0f / (float)N;
    for (int i = tid; i < BK; i += 256) sp[i] = g_pool[i] * invN;
    __syncthreads();
    {
        int hb = tid >> 4, hj = tid & 15;
        float acc = c1b[hj];
        #pragma unroll
        for (int k = 0; k < H2DIM; k++) acc = fmaf(sp[hb * H2DIM + k], c1W[k * H1DIM + hj], acc);
        sz[hb * H1DIM + hj] = fmaxf(acc, 0.0f);
    }
    __syncthreads();
    if (tid < BATCH * NCLS) {
        int hb = tid / NCLS, cc = tid % NCLS;
        float o = c2b[cc];
        #pragma unroll
        for (int jj = 0; jj < H1DIM; jj++) o = fmaf(sz[hb * H1DIM + jj], c2W[jj * NCLS + cc], o);
        out[tid] = o;
    }
    __syncthreads();
    // self-clean for next replay
    for (int i = tid; i < BK; i += 256) g_pool[i] = 0.0f;
    if (tid == 0) g_done = 0;
}

// ---------------- launch ----------------
extern "C" void kernel_launch(void* const* d_in, const int* in_sizes, int n_in,
                              void* d_out, int out_size) {
    const float* x    = (const float*)d_in[0];
    const int*   ei   = (const int*)  d_in[1];
    const float* ew   = (const float*)d_in[2];
    const float* encW = (const float*)d_in[3];
    const float* encb = (const float*)d_in[4];
    const float* W1   = (const float*)d_in[5];
    const float* b1   = (const float*)d_in[6];
    const float* W2   = (const float*)d_in[7];
    const float* b2   = (const float*)d_in[8];
    const float* c1W  = (const float*)d_in[9];
    const float* c1b  = (const float*)d_in[10];
    const float* c2W  = (const float*)d_in[11];
    const float* c2b  = (const float*)d_in[12];
    float* out = (float*)d_out;

    int E = in_sizes[2];        // edge_weight count
    int N = in_sizes[4];        // enc_b count

    int eb256 = (E + 255) / 256;

    k_deg <<<eb256, 256>>>(ei, ew, E);
    k_enc <<<(N + 127) / 128, 128>>>(x, encW, encb, N);
    k_l1  <<<(N + 15) / 16, 256>>>(N);
    k_l2  <<<(N + NPB - 1) / NPB, 256>>>(W1, b1, W2, b2, c1W, c1b, c2W, c2b, out, N);
}

// round 12
// speedup vs baseline: 1.0926x; 1.0926x over previous
#include <cuda_runtime.h>
#include <cuda_bf16.h>

// Problem constants (fixed shapes for this dataset)
#define BATCH   16
#define FDIM    128
#define NMAX    10000
#define EMAX    320000
#define H1DIM   16
#define H2DIM   32
#define NCLS    10
#define BK      (BATCH * H2DIM)   // 512  (pooled vector)
#define CAP     128               // bucket capacity per node (Poisson(32) tail ~ e^-85)
#define CAPP    132               // padded row stride for s_a (mult of 4, 132%32=4)

// ---------------- device scratch (no allocations allowed) ----------------
// All zero at module load; every kernel_launch leaves them zeroed again
// (g_deg re-zeroed by k_l1, g_pool/g_done by k_l2's last block).
__device__ unsigned long long g_deg[NMAX];   // packed: cnt<<40 | fixed-point weighted deg
__device__ float g_dis[NMAX];            // rsqrt(deg)
__device__ float g_self[NMAX];           // dis*dis
__device__ int   g_cnt[NMAX];            // unpacked edge count
__device__ int2  g_edge[NMAX * CAP];     // bucketed CSR: (row, edge_weight bits)
__device__ float g_h[NMAX * BATCH];      // encoder out, layout [n][b]
__device__ float g_agg1[NMAX * BATCH];   // layer1 scalar aggregation, layout [n][b]
__device__ float g_pool[BK];             // pooled sums
__device__ int   g_done;                 // l2 completion counter

// ---------------- K1: ONE atomic per edge: degree accumulate + bucket placement ----------------
__global__ void k_deg(const int* __restrict__ ei, const float* __restrict__ ew, int E) {
    int e = blockIdx.x * blockDim.x + threadIdx.x;
    if (e >= E) return;
    int r = ei[e];
    int c = ei[E + e];
    float w = ew[e];
    unsigned long long inc = (1ull << 40)
        | (unsigned long long)__float2uint_rn(w * 16777216.0f);
    unsigned long long old = atomicAdd(&g_deg[c], inc);
    int slot = (int)(old >> 40);
    if (slot < CAP)
        g_edge[c * CAP + slot] = make_int2(r, __float_as_int(w));
}

// ---------------- K2: encoder + deg unpack.  h[n][b] = x[b,:]·enc_W[:,n] + enc_b[n] ----------------
__global__ void k_enc(const float* __restrict__ x, const float* __restrict__ encW,
                      const float* __restrict__ encb, int N) {
    __shared__ float sx[BATCH * FDIM];
    int tid = threadIdx.x;
    for (int i = tid; i < BATCH * FDIM; i += blockDim.x) sx[i] = x[i];
    __syncthreads();
    int n = blockIdx.x * blockDim.x + tid;
    if (n >= N) return;

    {   // unpack degree -> dis / self / cnt
        unsigned long long v = g_deg[n];
        int cnt = (int)(v >> 40);
        float deg = 1.0f + (float)(v & 0xFFFFFFFFFFull) * (1.0f / 16777216.0f);
        float d = rsqrtf(deg);
        g_dis[n] = d;
        g_self[n] = d * d;
        g_cnt[n] = cnt < CAP ? cnt : CAP;
    }

    float acc[BATCH];
    #pragma unroll
    for (int b = 0; b < BATCH; b++) acc[b] = 0.0f;
    #pragma unroll 16
    for (int f = 0; f < FDIM; f++) {
        float w = encW[(size_t)f * N + n];
        #pragma unroll
        for (int b = 0; b < BATCH; b++) acc[b] = fmaf(sx[b * FDIM + f], w, acc[b]);
    }
    float eb = encb[n];
    #pragma unroll
    for (int b = 0; b < BATCH; b++) g_h[n * BATCH + b] = acc[b] + eb;
}

// ---------------- K3: layer1 scalar aggregation (half-warp shfl, pipelined) ----------------
__global__ void k_l1(int N) {
    int tid = threadIdx.x;
    int lane = tid & 31;
    int b = lane & 15;
    unsigned hmask = 0xFFFFu << (lane & 16);     // this half-warp's mask
    int c = blockIdx.x * 16 + (tid >> 4);
    if (c >= N) return;

    float dc = g_dis[c];
    float agg  = g_self[c] * g_h[c * BATCH + b];
    float agg2 = 0.0f;
    int base = c * CAP;
    int cnt = g_cnt[c];

    bool valid = b < cnt;
    int2  ed = valid ? g_edge[base + b] : make_int2(0, 0);
    float dr = valid ? g_dis[ed.x] : 0.0f;

    for (int bs = 0; bs < cnt; bs += 16) {
        float nm = valid ? dr * __int_as_float(ed.y) * dc : 0.0f;
        int   rx = ed.x;
        bool v2 = (bs + 16 + b) < cnt;
        int2  ed2 = v2 ? g_edge[base + bs + 16 + b] : make_int2(0, 0);
        float dr2 = v2 ? g_dis[ed2.x] : 0.0f;
        #pragma unroll
        for (int e = 0; e < 16; e += 2) {
            int   r0 = __shfl_sync(hmask, rx, e,     16);
            float n0 = __shfl_sync(hmask, nm, e,     16);
            int   r1 = __shfl_sync(hmask, rx, e + 1, 16);
            float n1 = __shfl_sync(hmask, nm, e + 1, 16);
            agg  = fmaf(n0, g_h[r0 * BATCH + b], agg);
            agg2 = fmaf(n1, g_h[r1 * BATCH + b], agg2);
        }
        ed = ed2; dr = dr2; valid = v2;
    }
    g_agg1[c * BATCH + b] = agg + agg2;
    if (b == 0) g_deg[c] = 0ull;                 // self-clean for next replay
}

// ---------------- K4: layer2 + fused head (last-block). ----------------
// s_a transposed to [b][p] (stride CAPP) -> float4 LDS in the hot loop.
#define NPB 4
__global__ void k_l2(const float* __restrict__ W1, const float* __restrict__ b1,
                     const float* __restrict__ W2, const float* __restrict__ b2,
                     const float* __restrict__ c1W, const float* __restrict__ c1b,
                     const float* __restrict__ c2W, const float* __restrict__ c2b,
                     float* __restrict__ out, int N) {
    __shared__ __align__(16) float s_a[16 * CAPP];   // [b][p] padded (8.25KB)
    __shared__ __align__(16) float s_norm[CAP];
    __shared__ int   s_row[CAP];
    __shared__ float sW2[H1DIM * H2DIM];
    __shared__ float sb2[H2DIM];
    int tid = threadIdx.x;                 // = b*16 + j
    int b = tid >> 4, j = tid & 15;
    unsigned hmask = 0xFFFFu << (tid & 16);
    float w1 = W1[j];
    float bb1 = b1[j];
    if (tid < H2DIM) sb2[tid] = b2[tid];
    for (int i = tid; i < H1DIM * H2DIM; i += 256) sW2[i] = W2[i];
    __syncthreads();

    float ps0 = 0.0f, ps1 = 0.0f;
    int c0 = blockIdx.x * NPB;
    for (int i = 0; i < NPB; i++) {
        int c = c0 + i;
        if (c >= N) break;                  // uniform across block
        int base = c * CAP;
        int m = g_cnt[c];                   // <= CAP: exactly one chunk
        float dcc = g_dis[c];
        float acc = g_self[c] * fmaxf(fmaf(g_agg1[c * BATCH + b], w1, bb1), 0.0f);

        if (tid < m) {
            int2 ed = g_edge[base + tid];
            s_row[tid]  = ed.x;
            s_norm[tid] = g_dis[ed.x] * __int_as_float(ed.y) * dcc;
        }
        int m4 = (m + 3) & ~3;              // zero-pad norms to float4 boundary
        if (tid >= m && tid < m4) s_norm[tid] = 0.0f;
        __syncthreads();
        {
            int f = tid & 15, ei = tid >> 4;   // 16 edges per pass, 8 passes
            #pragma unroll
            for (int pass = 0; pass < 8; pass++) {
                int ep = ei + pass * 16;
                if (ep < m) {
                    int r = s_row[ep];                           // smem broadcast
                    s_a[f * CAPP + ep] = g_agg1[r * BATCH + f];  // transposed store
                }
            }
        }
        __syncthreads();
        {
            float a0 = 0.f, a1 = 0.f, a2 = 0.f, a3 = 0.f;
            const float4* av4 = (const float4*)&s_a[b * CAPP];
            const float4* nv4 = (const float4*)s_norm;
            for (int p4 = 0; p4 < m4 >> 2; p4++) {
                float4 av = av4[p4];                 // LDS.128: 4 edges' a
                float4 nv = nv4[p4];                 // LDS.128: 4 norms (zero-padded)
                a0 = fmaf(nv.x, fmaxf(fmaf(av.x, w1, bb1), 0.f), a0);
                a1 = fmaf(nv.y, fmaxf(fmaf(av.y, w1, bb1), 0.f), a1);
                a2 = fmaf(nv.z, fmaxf(fmaf(av.z, w1, bb1), 0.f), a2);
                a3 = fmaf(nv.w, fmaxf(fmaf(av.w, w1, bb1), 0.f), a3);
            }
            acc += (a0 + a1) + (a2 + a3);
        }
        // epilogue via half-warp shfl (threads b*16..b*16+15 are one half-warp)
        float v0 = sb2[j], v1 = sb2[j + 16];
        #pragma unroll
        for (int jj = 0; jj < H1DIM; jj++) {
            float a = __shfl_sync(hmask, acc, jj, 16);
            v0 = fmaf(a, sW2[jj * H2DIM + j],      v0);
            v1 = fmaf(a, sW2[jj * H2DIM + j + 16], v1);
        }
        ps0 += fmaxf(v0, 0.0f);
        ps1 += fmaxf(v1, 0.0f);
        __syncthreads();                    // staging arrays reused next node
    }
    atomicAdd(&g_pool[b * H2DIM + j],      ps0);
    atomicAdd(&g_pool[b * H2DIM + j + 16], ps1);

    // ---- fused classifier head: last block to finish runs it ----
    __threadfence();
    __shared__ int s_last;
    if (tid == 0) {
        int d = atomicAdd(&g_done, 1);
        s_last = (d == (int)gridDim.x - 1);
    }
    __syncthreads();
    if (!s_last) return;

    __shared__ float sp[BK];
    __shared__ float sz[BATCH * H1DIM];
    float invN = 1.0f / (float)N;
    for (int i = tid; i < BK; i += 256) sp[i] = g_pool[i] * invN;
    __syncthreads();
    {
        int hb = tid >> 4, hj = tid & 15;
        float acc = c1b[hj];
        #pragma unroll
        for (int k = 0; k < H2DIM; k++) acc = fmaf(sp[hb * H2DIM + k], c1W[k * H1DIM + hj], acc);
        sz[hb * H1DIM + hj] = fmaxf(acc, 0.0f);
    }
    __syncthreads();
    if (tid < BATCH * NCLS) {
        int hb = tid / NCLS, cc = tid % NCLS;
        float o = c2b[cc];
        #pragma unroll
        for (int jj = 0; jj < H1DIM; jj++) o = fmaf(sz[hb * H1DIM + jj], c2W[jj * NCLS + cc], o);
        out[tid] = o;
    }
    __syncthreads();
    // self-clean for next replay
    for (int i = tid; i < BK; i += 256) g_pool[i] = 0.0f;
    if (tid == 0) g_done = 0;
}

// ---------------- launch ----------------
extern "C" void kernel_launch(void* const* d_in, const int* in_sizes, int n_in,
                              void* d_out, int out_size) {
    const float* x    = (const float*)d_in[0];
    const int*   ei   = (const int*)  d_in[1];
    const float* ew   = (const float*)d_in[2];
    const float* encW = (const float*)d_in[3];
    const float* encb = (const float*)d_in[4];
    const float* W1   = (const float*)d_in[5];
    const float* b1   = (const float*)d_in[6];
    const float* W2   = (const float*)d_in[7];
    const float* b2   = (const float*)d_in[8];
    const float* c1W  = (const float*)d_in[9];
    const float* c1b  = (const float*)d_in[10];
    const float* c2W  = (const float*)d_in[11];
    const float* c2b  = (const float*)d_in[12];
    float* out = (float*)d_out;

    int E = in_sizes[2];        // edge_weight count
    int N = in_sizes[4];        // enc_b count

    int eb256 = (E + 255) / 256;

    k_deg <<<eb256, 256>>>(ei, ew, E);
    k_enc <<<(N + 127) / 128, 128>>>(x, encW, encb, N);
    k_l1  <<<(N + 15) / 16, 256>>>(N);
    k_l2  <<<(N + NPB - 1) / NPB, 256>>>(W1, b1, W2, b2, c1W, c1b, c2W, c2b, out, N);
}

// round 14
// speedup vs baseline: 1.1100x; 1.0159x over previous
#include <cuda_runtime.h>
#include <cuda_bf16.h>

// Problem constants (fixed shapes for this dataset)
#define BATCH   16
#define FDIM    128
#define NMAX    10000
#define EMAX    320000
#define H1DIM   16
#define H2DIM   32
#define NCLS    10
#define BK      (BATCH * H2DIM)   // 512  (pooled vector)
#define CAP     128               // bucket capacity per node (Poisson(32) tail ~ e^-85)
#define CAPP    132               // padded row stride for s_a (132*4=528B, 16B aligned)

// packed f32x2 helpers (sm_103a): FFMA2 via PTX; relu via scalar max on pair halves
#define FMA2(d, a, b, c) asm("fma.rn.f32x2 %0, %1, %2, %3;" : "=l"(d) : "l"(a), "l"(b), "l"(c))
#define RELU2(d, x) asm("{\n\t.reg .f32 lo, hi;\n\tmov.b64 {lo, hi}, %1;\n\t" \
                        "max.f32 lo, lo, 0f00000000;\n\tmax.f32 hi, hi, 0f00000000;\n\t" \
                        "mov.b64 %0, {lo, hi};\n\t}" : "=l"(d) : "l"(x))
#define PACK2(d, lo, hi) asm("mov.b64 %0, {%1, %2};" : "=l"(d) : "r"(lo), "r"(hi))

// ---------------- device scratch (no allocations allowed) ----------------
// All zero at module load; every kernel_launch leaves them zeroed again
// (g_deg re-zeroed by k_l1, g_pool/g_done by k_l2's last block).
__device__ unsigned long long g_deg[NMAX];   // packed: cnt<<40 | fixed-point weighted deg
__device__ float g_dis[NMAX];            // rsqrt(deg)
__device__ float g_self[NMAX];           // dis*dis
__device__ int   g_cnt[NMAX];            // unpacked edge count
__device__ int2  g_edge[NMAX * CAP];     // bucketed CSR: (row, edge_weight bits)
__device__ float g_h[NMAX * BATCH];      // encoder out, layout [n][b]
__device__ float g_agg1[NMAX * BATCH];   // layer1 scalar aggregation, layout [n][b]
__device__ float g_pool[BK];             // pooled sums
__device__ int   g_done;                 // l2 completion counter

// ---------------- K1: ONE atomic per edge: degree accumulate + bucket placement ----------------
__global__ void k_deg(const int* __restrict__ ei, const float* __restrict__ ew, int E) {
    int e = blockIdx.x * blockDim.x + threadIdx.x;
    if (e >= E) return;
    int r = ei[e];
    int c = ei[E + e];
    float w = ew[e];
    unsigned long long inc = (1ull << 40)
        | (unsigned long long)__float2uint_rn(w * 16777216.0f);
    unsigned long long old = atomicAdd(&g_deg[c], inc);
    int slot = (int)(old >> 40);
    if (slot < CAP)
        g_edge[c * CAP + slot] = make_int2(r, __float_as_int(w));
}

// ---------------- K2: encoder + deg unpack.  h[n][b] = x[b,:]·enc_W[:,n] + enc_b[n] ----------------
__global__ void k_enc(const float* __restrict__ x, const float* __restrict__ encW,
                      const float* __restrict__ encb, int N) {
    __shared__ float sx[BATCH * FDIM];
    int tid = threadIdx.x;
    for (int i = tid; i < BATCH * FDIM; i += blockDim.x) sx[i] = x[i];
    __syncthreads();
    int n = blockIdx.x * blockDim.x + tid;
    if (n >= N) return;

    {   // unpack degree -> dis / self / cnt
        unsigned long long v = g_deg[n];
        int cnt = (int)(v >> 40);
        float deg = 1.0f + (float)(v & 0xFFFFFFFFFFull) * (1.0f / 16777216.0f);
        float d = rsqrtf(deg);
        g_dis[n] = d;
        g_self[n] = d * d;
        g_cnt[n] = cnt < CAP ? cnt : CAP;
    }

    float acc[BATCH];
    #pragma unroll
    for (int b = 0; b < BATCH; b++) acc[b] = 0.0f;
    #pragma unroll 16
    for (int f = 0; f < FDIM; f++) {
        float w = encW[(size_t)f * N + n];
        #pragma unroll
        for (int b = 0; b < BATCH; b++) acc[b] = fmaf(sx[b * FDIM + f], w, acc[b]);
    }
    float eb = encb[n];
    #pragma unroll
    for (int b = 0; b < BATCH; b++) g_h[n * BATCH + b] = acc[b] + eb;
}

// ---------------- K3: layer1 scalar aggregation (half-warp shfl, pipelined) ----------------
__global__ void k_l1(int N) {
    int tid = threadIdx.x;
    int lane = tid & 31;
    int b = lane & 15;
    unsigned hmask = 0xFFFFu << (lane & 16);     // this half-warp's mask
    int c = blockIdx.x * 16 + (tid >> 4);
    if (c >= N) return;

    float dc = g_dis[c];
    float agg  = g_self[c] * g_h[c * BATCH + b];
    float agg2 = 0.0f;
    int base = c * CAP;
    int cnt = g_cnt[c];

    bool valid = b < cnt;
    int2  ed = valid ? g_edge[base + b] : make_int2(0, 0);
    float dr = valid ? g_dis[ed.x] : 0.0f;

    for (int bs = 0; bs < cnt; bs += 16) {
        float nm = valid ? dr * __int_as_float(ed.y) * dc : 0.0f;
        int   rx = ed.x;
        bool v2 = (bs + 16 + b) < cnt;
        int2  ed2 = v2 ? g_edge[base + bs + 16 + b] : make_int2(0, 0);
        float dr2 = v2 ? g_dis[ed2.x] : 0.0f;
        #pragma unroll
        for (int e = 0; e < 16; e += 2) {
            int   r0 = __shfl_sync(hmask, rx, e,     16);
            float n0 = __shfl_sync(hmask, nm, e,     16);
            int   r1 = __shfl_sync(hmask, rx, e + 1, 16);
            float n1 = __shfl_sync(hmask, nm, e + 1, 16);
            agg  = fmaf(n0, g_h[r0 * BATCH + b], agg);
            agg2 = fmaf(n1, g_h[r1 * BATCH + b], agg2);
        }
        ed = ed2; dr = dr2; valid = v2;
    }
    g_agg1[c * BATCH + b] = agg + agg2;
    if (b == 0) g_deg[c] = 0ull;                 // self-clean for next replay
}

// ---------------- K4: layer2 + fused head (last-block). ----------------
// s_a transposed to [b][p] (stride CAPP); hot loop: FFMA2 expand, scalar relu, FFMA2 acc.
#define NPB 4
__global__ void k_l2(const float* __restrict__ W1, const float* __restrict__ b1,
                     const float* __restrict__ W2, const float* __restrict__ b2,
                     const float* __restrict__ c1W, const float* __restrict__ c1b,
                     const float* __restrict__ c2W, const float* __restrict__ c2b,
                     float* __restrict__ out, int N) {
    __shared__ __align__(16) float s_a[16 * CAPP];   // [b][p] padded (8.25KB)
    __shared__ __align__(16) float s_norm[CAP];
    __shared__ int   s_row[CAP];
    __shared__ float sW2[H1DIM * H2DIM];
    __shared__ float sb2[H2DIM];
    int tid = threadIdx.x;                 // = b*16 + j
    int b = tid >> 4, j = tid & 15;
    unsigned hmask = 0xFFFFu << (tid & 16);
    float w1 = W1[j];
    float bb1 = b1[j];
    unsigned long long w1p, b1p;
    PACK2(w1p, __float_as_uint(w1),  __float_as_uint(w1));
    PACK2(b1p, __float_as_uint(bb1), __float_as_uint(bb1));
    if (tid < H2DIM) sb2[tid] = b2[tid];
    for (int i = tid; i < H1DIM * H2DIM; i += 256) sW2[i] = W2[i];
    __syncthreads();

    float ps0 = 0.0f, ps1 = 0.0f;
    int c0 = blockIdx.x * NPB;
    for (int i = 0; i < NPB; i++) {
        int c = c0 + i;
        if (c >= N) break;                  // uniform across block
        int base = c * CAP;
        int m = g_cnt[c];                   // <= CAP: exactly one chunk
        float dcc = g_dis[c];
        float acc = g_self[c] * fmaxf(fmaf(g_agg1[c * BATCH + b], w1, bb1), 0.0f);

        if (tid < m) {
            int2 ed = g_edge[base + tid];
            s_row[tid]  = ed.x;
            s_norm[tid] = g_dis[ed.x] * __int_as_float(ed.y) * dcc;
        }
        int m4 = (m + 3) & ~3;              // zero-pad norms to float4 boundary
        if (tid >= m && tid < m4) s_norm[tid] = 0.0f;
        __syncthreads();
        {
            int f = tid & 15, ei = tid >> 4;   // 16 edges per pass, 8 passes
            #pragma unroll
            for (int pass = 0; pass < 8; pass++) {
                int ep = ei + pass * 16;
                if (ep < m) {
                    int r = s_row[ep];                           // smem broadcast
                    s_a[f * CAPP + ep] = g_agg1[r * BATCH + f];  // transposed store
                }
            }
        }
        __syncthreads();
        {
            unsigned long long accA = 0ull, accB = 0ull;
            const ulonglong2* av2 = (const ulonglong2*)&s_a[b * CAPP];
            const ulonglong2* nv2 = (const ulonglong2*)s_norm;
            for (int p4 = 0; p4 < m4 >> 2; p4++) {
                ulonglong2 av = av2[p4];                 // LDS.128: 4 edges' a (2 x f32x2)
                ulonglong2 nv = nv2[p4];                 // LDS.128: 4 norms (zero-padded)
                unsigned long long x0, x1;
                FMA2(x0, av.x, w1p, b1p);
                FMA2(x1, av.y, w1p, b1p);
                RELU2(x0, x0);
                RELU2(x1, x1);
                FMA2(accA, nv.x, x0, accA);
                FMA2(accB, nv.y, x1, accB);
            }
            float2 fa = *(float2*)&accA;
            float2 fb = *(float2*)&accB;
            acc += (fa.x + fa.y) + (fb.x + fb.y);
        }
        // epilogue via half-warp shfl (threads b*16..b*16+15 are one half-warp)
        float v0 = sb2[j], v1 = sb2[j + 16];
        #pragma unroll
        for (int jj = 0; jj < H1DIM; jj++) {
            float a = __shfl_sync(hmask, acc, jj, 16);
            v0 = fmaf(a, sW2[jj * H2DIM + j],      v0);
            v1 = fmaf(a, sW2[jj * H2DIM + j + 16], v1);
        }
        ps0 += fmaxf(v0, 0.0f);
        ps1 += fmaxf(v1, 0.0f);
        __syncthreads();                    // staging arrays reused next node
    }
    atomicAdd(&g_pool[b * H2DIM + j],      ps0);
    atomicAdd(&g_pool[b * H2DIM + j + 16], ps1);

    // ---- fused classifier head: last block to finish runs it ----
    __threadfence();
    __shared__ int s_last;
    if (tid == 0) {
        int d = atomicAdd(&g_done, 1);
        s_last = (d == (int)gridDim.x - 1);
    }
    __syncthreads();
    if (!s_last) return;

    __shared__ float sp[BK];
    __shared__ float sz[BATCH * H1DIM];
    float invN = 1.0f / (float)N;
    for (int i = tid; i < BK; i += 256) sp[i] = g_pool[i] * invN;
    __syncthreads();
    {
        int hb = tid >> 4, hj = tid & 15;
        float acc = c1b[hj];
        #pragma unroll
        for (int k = 0; k < H2DIM; k++) acc = fmaf(sp[hb * H2DIM + k], c1W[k * H1DIM + hj], acc);
        sz[hb * H1DIM + hj] = fmaxf(acc, 0.0f);
    }
    __syncthreads();
    if (tid < BATCH * NCLS) {
        int hb = tid / NCLS, cc = tid % NCLS;
        float o = c2b[cc];
        #pragma unroll
        for (int jj = 0; jj < H1DIM; jj++) o = fmaf(sz[hb * H1DIM + jj], c2W[jj * NCLS + cc], o);
        out[tid] = o;
    }
    __syncthreads();
    // self-clean for next replay
    for (int i = tid; i < BK; i += 256) g_pool[i] = 0.0f;
    if (tid == 0) g_done = 0;
}

// ---------------- launch ----------------
extern "C" void kernel_launch(void* const* d_in, const int* in_sizes, int n_in,
                              void* d_out, int out_size) {
    const float* x    = (const float*)d_in[0];
    const int*   ei   = (const int*)  d_in[1];
    const float* ew   = (const float*)d_in[2];
    const float* encW = (const float*)d_in[3];
    const float* encb = (const float*)d_in[4];
    const float* W1   = (const float*)d_in[5];
    const float* b1   = (const float*)d_in[6];
    const float* W2   = (const float*)d_in[7];
    const float* b2   = (const float*)d_in[8];
    const float* c1W  = (const float*)d_in[9];
    const float* c1b  = (const float*)d_in[10];
    const float* c2W  = (const float*)d_in[11];
    const float* c2b  = (const float*)d_in[12];
    float* out = (float*)d_out;

    int E = in_sizes[2];        // edge_weight count
    int N = in_sizes[4];        // enc_b count

    int eb256 = (E + 255) / 256;

    k_deg <<<eb256, 256>>>(ei, ew, E);
    k_enc <<<(N + 127) / 128, 128>>>(x, encW, encb, N);
    k_l1  <<<(N + 15) / 16, 256>>>(N);
    k_l2  <<<(N + NPB - 1) / NPB, 256>>>(W1, b1, W2, b2, c1W, c1b, c2W, c2b, out, N);
}

// round 15
// speedup vs baseline: 1.2137x; 1.0935x over previous
#include <cuda_runtime.h>
#include <cuda_bf16.h>

// Problem constants (fixed shapes for this dataset)
#define BATCH   16
#define FDIM    128
#define NMAX    10000
#define EMAX    320000
#define H1DIM   16
#define H2DIM   32
#define NCLS    10
#define BK      (BATCH * H2DIM)   // 512  (pooled vector)
#define CAP     128               // bucket capacity per node (Poisson(32) tail ~ e^-85)
#define CAPP    132               // padded row stride for s_a (132*4=528B, 16B aligned)

// packed f32x2 helpers (sm_103a): FFMA2 via PTX; relu via scalar max on pair halves
#define FMA2(d, a, b, c) asm("fma.rn.f32x2 %0, %1, %2, %3;" : "=l"(d) : "l"(a), "l"(b), "l"(c))
#define RELU2(d, x) asm("{\n\t.reg .f32 lo, hi;\n\tmov.b64 {lo, hi}, %1;\n\t" \
                        "max.f32 lo, lo, 0f00000000;\n\tmax.f32 hi, hi, 0f00000000;\n\t" \
                        "mov.b64 %0, {lo, hi};\n\t}" : "=l"(d) : "l"(x))
#define PACK2(d, lo, hi) asm("mov.b64 %0, {%1, %2};" : "=l"(d) : "r"(lo), "r"(hi))

// ---------------- device scratch (no allocations allowed) ----------------
// All zero at module load; every kernel_launch leaves them zeroed again
// (g_deg re-zeroed by k_l1, g_pool/g_done by k_l2's last block).
__device__ unsigned long long g_deg[NMAX];   // packed: cnt<<40 | fixed-point weighted deg
__device__ float g_dis[NMAX];            // rsqrt(deg)
__device__ float g_self[NMAX];           // dis*dis
__device__ int   g_cnt[NMAX];            // unpacked edge count
__device__ int2  g_edge[NMAX * CAP];     // bucketed CSR: (row, edge_weight bits)
__device__ float g_norm[NMAX * CAP];     // finalized per-edge norms (written by k_l1)
__device__ float g_h[NMAX * BATCH];      // encoder out, layout [n][b]
__device__ float g_agg1[NMAX * BATCH];   // layer1 scalar aggregation, layout [n][b]
__device__ float g_pool[BK];             // pooled sums
__device__ int   g_done;                 // l2 completion counter

// ---------------- K1: ONE atomic per edge: degree accumulate + bucket placement ----------------
__global__ void k_deg(const int* __restrict__ ei, const float* __restrict__ ew, int E) {
    int e = blockIdx.x * blockDim.x + threadIdx.x;
    if (e >= E) return;
    int r = ei[e];
    int c = ei[E + e];
    float w = ew[e];
    unsigned long long inc = (1ull << 40)
        | (unsigned long long)__float2uint_rn(w * 16777216.0f);
    unsigned long long old = atomicAdd(&g_deg[c], inc);
    int slot = (int)(old >> 40);
    if (slot < CAP)
        g_edge[c * CAP + slot] = make_int2(r, __float_as_int(w));
}

// ---------------- K2: encoder + deg unpack.  h[n][b] = x[b,:]·enc_W[:,n] + enc_b[n] ----------------
__global__ void k_enc(const float* __restrict__ x, const float* __restrict__ encW,
                      const float* __restrict__ encb, int N) {
    __shared__ float sx[BATCH * FDIM];
    int tid = threadIdx.x;
    for (int i = tid; i < BATCH * FDIM; i += blockDim.x) sx[i] = x[i];
    __syncthreads();
    int n = blockIdx.x * blockDim.x + tid;
    if (n >= N) return;

    {   // unpack degree -> dis / self / cnt
        unsigned long long v = g_deg[n];
        int cnt = (int)(v >> 40);
        float deg = 1.0f + (float)(v & 0xFFFFFFFFFFull) * (1.0f / 16777216.0f);
        float d = rsqrtf(deg);
        g_dis[n] = d;
        g_self[n] = d * d;
        g_cnt[n] = cnt < CAP ? cnt : CAP;
    }

    float acc[BATCH];
    #pragma unroll
    for (int b = 0; b < BATCH; b++) acc[b] = 0.0f;
    #pragma unroll 16
    for (int f = 0; f < FDIM; f++) {
        float w = encW[(size_t)f * N + n];
        #pragma unroll
        for (int b = 0; b < BATCH; b++) acc[b] = fmaf(sx[b * FDIM + f], w, acc[b]);
    }
    float eb = encb[n];
    #pragma unroll
    for (int b = 0; b < BATCH; b++) g_h[n * BATCH + b] = acc[b] + eb;
}

// ---------------- K3: layer1 scalar aggregation (half-warp shfl, pipelined) ----------------
// Also emits finalized per-edge norms (coalesced) for k_l2.
__global__ void k_l1(int N) {
    int tid = threadIdx.x;
    int lane = tid & 31;
    int b = lane & 15;
    unsigned hmask = 0xFFFFu << (lane & 16);     // this half-warp's mask
    int c = blockIdx.x * 16 + (tid >> 4);
    if (c >= N) return;

    float dc = g_dis[c];
    float agg  = g_self[c] * g_h[c * BATCH + b];
    float agg2 = 0.0f;
    int base = c * CAP;
    int cnt = g_cnt[c];

    bool valid = b < cnt;
    int2  ed = valid ? g_edge[base + b] : make_int2(0, 0);
    float dr = valid ? g_dis[ed.x] : 0.0f;

    for (int bs = 0; bs < cnt; bs += 16) {
        float nm = valid ? dr * __int_as_float(ed.y) * dc : 0.0f;
        int   rx = ed.x;
        if (valid) g_norm[base + bs + b] = nm;       // coalesced 64B per half-warp
        bool v2 = (bs + 16 + b) < cnt;
        int2  ed2 = v2 ? g_edge[base + bs + 16 + b] : make_int2(0, 0);
        float dr2 = v2 ? g_dis[ed2.x] : 0.0f;
        #pragma unroll
        for (int e = 0; e < 16; e += 2) {
            int   r0 = __shfl_sync(hmask, rx, e,     16);
            float n0 = __shfl_sync(hmask, nm, e,     16);
            int   r1 = __shfl_sync(hmask, rx, e + 1, 16);
            float n1 = __shfl_sync(hmask, nm, e + 1, 16);
            agg  = fmaf(n0, g_h[r0 * BATCH + b], agg);
            agg2 = fmaf(n1, g_h[r1 * BATCH + b], agg2);
        }
        ed = ed2; dr = dr2; valid = v2;
    }
    g_agg1[c * BATCH + b] = agg + agg2;
    if (b == 0) g_deg[c] = 0ull;                 // self-clean for next replay
}

// ---------------- K4: layer2 + fused head (last-block). ----------------
// Wavefront-lean: coalesced norm load, dynamic staging, smem epilogue (no shfl).
#define NPB 4
__global__ void k_l2(const float* __restrict__ W1, const float* __restrict__ b1,
                     const float* __restrict__ W2, const float* __restrict__ b2,
                     const float* __restrict__ c1W, const float* __restrict__ c1b,
                     const float* __restrict__ c2W, const float* __restrict__ c2b,
                     float* __restrict__ out, int N) {
    __shared__ __align__(16) float s_a[16 * CAPP];   // [b][p] padded (8.25KB)
    __shared__ __align__(16) float s_norm[CAP];
    __shared__ __align__(16) float sagg[256];        // per-node aggregated h1 [b][j]
    __shared__ int   s_row[CAP];
    __shared__ float sW2[H1DIM * H2DIM];
    __shared__ float sb2[H2DIM];
    int tid = threadIdx.x;                 // = b*16 + j
    int b = tid >> 4, j = tid & 15;
    float w1 = W1[j];
    float bb1 = b1[j];
    unsigned long long w1p, b1p;
    PACK2(w1p, __float_as_uint(w1),  __float_as_uint(w1));
    PACK2(b1p, __float_as_uint(bb1), __float_as_uint(bb1));
    if (tid < H2DIM) sb2[tid] = b2[tid];
    for (int i = tid; i < H1DIM * H2DIM; i += 256) sW2[i] = W2[i];
    __syncthreads();

    float ps0 = 0.0f, ps1 = 0.0f;
    int c0 = blockIdx.x * NPB;
    for (int i = 0; i < NPB; i++) {
        int c = c0 + i;
        if (c >= N) break;                  // uniform across block
        int base = c * CAP;
        int m = g_cnt[c];                   // <= CAP: exactly one chunk
        float acc = g_self[c] * fmaxf(fmaf(g_agg1[c * BATCH + b], w1, bb1), 0.0f);

        if (tid < m) {
            s_row[tid]  = g_edge[base + tid].x;   // coalesced LDG.64
            s_norm[tid] = g_norm[base + tid];     // coalesced LDG.32 (finalized in k_l1)
        }
        int m4 = (m + 3) & ~3;              // zero-pad norms to float4 boundary
        if (tid >= m && tid < m4) s_norm[tid] = 0.0f;
        __syncthreads();
        {   // dynamic staging: thread (f = tid&15) fills s_a rows for ep = tid>>4 step 16
            int f = tid & 15;
            for (int ep = tid >> 4; ep < m; ep += 16)
                s_a[f * CAPP + ep] = g_agg1[s_row[ep] * BATCH + f];
        }
        __syncthreads();
        {
            unsigned long long accA = 0ull, accB = 0ull;
            const ulonglong2* av2 = (const ulonglong2*)&s_a[b * CAPP];
            const ulonglong2* nv2 = (const ulonglong2*)s_norm;
            for (int p4 = 0; p4 < m4 >> 2; p4++) {
                ulonglong2 av = av2[p4];                 // LDS.128: 4 edges' a (2 x f32x2)
                ulonglong2 nv = nv2[p4];                 // LDS.128: 4 norms (zero-padded)
                unsigned long long x0, x1;
                FMA2(x0, av.x, w1p, b1p);
                FMA2(x1, av.y, w1p, b1p);
                RELU2(x0, x0);
                RELU2(x1, x1);
                FMA2(accA, nv.x, x0, accA);
                FMA2(accB, nv.y, x1, accB);
            }
            float2 fa = *(float2*)&accA;
            float2 fb = *(float2*)&accB;
            acc += (fa.x + fa.y) + (fb.x + fb.y);
        }
        // epilogue via smem broadcast (1 STS + 4 LDS.128 instead of 16 shfl)
        sagg[tid] = acc;
        __syncthreads();
        {
            float v0 = sb2[j], v1 = sb2[j + 16];
            const float4* sg = (const float4*)&sagg[b * H1DIM];
            #pragma unroll
            for (int q = 0; q < 4; q++) {
                float4 av = sg[q];
                int jj = q * 4;
                v0 = fmaf(av.x, sW2[(jj + 0) * H2DIM + j],      v0);
                v1 = fmaf(av.x, sW2[(jj + 0) * H2DIM + j + 16], v1);
                v0 = fmaf(av.y, sW2[(jj + 1) * H2DIM + j],      v0);
                v1 = fmaf(av.y, sW2[(jj + 1) * H2DIM + j + 16], v1);
                v0 = fmaf(av.z, sW2[(jj + 2) * H2DIM + j],      v0);
                v1 = fmaf(av.z, sW2[(jj + 2) * H2DIM + j + 16], v1);
                v0 = fmaf(av.w, sW2[(jj + 3) * H2DIM + j],      v0);
                v1 = fmaf(av.w, sW2[(jj + 3) * H2DIM + j + 16], v1);
            }
            ps0 += fmaxf(v0, 0.0f);
            ps1 += fmaxf(v1, 0.0f);
        }
        // no extra sync needed: s_row/s_norm/s_a rewritten only after next node's
        // syncs; sagg rewritten only after next node's hot loop (gated by 2 syncs).
    }
    atomicAdd(&g_pool[b * H2DIM + j],      ps0);
    atomicAdd(&g_pool[b * H2DIM + j + 16], ps1);

    // ---- fused classifier head: last block to finish runs it ----
    __threadfence();
    __shared__ int s_last;
    if (tid == 0) {
        int d = atomicAdd(&g_done, 1);
        s_last = (d == (int)gridDim.x - 1);
    }
    __syncthreads();
    if (!s_last) return;

    __shared__ float sp[BK];
    __shared__ float sz[BATCH * H1DIM];
    float invN = 1.0f / (float)N;
    for (int i = tid; i < BK; i += 256) sp[i] = g_pool[i] * invN;
    __syncthreads();
    {
        int hb = tid >> 4, hj = tid & 15;
        float acc = c1b[hj];
        #pragma unroll
        for (int k = 0; k < H2DIM; k++) acc = fmaf(sp[hb * H2DIM + k], c1W[k * H1DIM + hj], acc);
        sz[hb * H1DIM + hj] = fmaxf(acc, 0.0f);
    }
    __syncthreads();
    if (tid < BATCH * NCLS) {
        int hb = tid / NCLS, cc = tid % NCLS;
        float o = c2b[cc];
        #pragma unroll
        for (int jj = 0; jj < H1DIM; jj++) o = fmaf(sz[hb * H1DIM + jj], c2W[jj * NCLS + cc], o);
        out[tid] = o;
    }
    __syncthreads();
    // self-clean for next replay
    for (int i = tid; i < BK; i += 256) g_pool[i] = 0.0f;
    if (tid == 0) g_done = 0;
}

// ---------------- launch ----------------
extern "C" void kernel_launch(void* const* d_in, const int* in_sizes, int n_in,
                              void* d_out, int out_size) {
    const float* x    = (const float*)d_in[0];
    const int*   ei   = (const int*)  d_in[1];
    const float* ew   = (const float*)d_in[2];
    const float* encW = (const float*)d_in[3];
    const float* encb = (const float*)d_in[4];
    const float* W1   = (const float*)d_in[5];
    const float* b1   = (const float*)d_in[6];
    const float* W2   = (const float*)d_in[7];
    const float* b2   = (const float*)d_in[8];
    const float* c1W  = (const float*)d_in[9];
    const float* c1b  = (const float*)d_in[10];
    const float* c2W  = (const float*)d_in[11];
    const float* c2b  = (const float*)d_in[12];
    float* out = (float*)d_out;

    int E = in_sizes[2];        // edge_weight count
    int N = in_sizes[4];        // enc_b count

    int eb256 = (E + 255) / 256;

    k_deg <<<eb256, 256>>>(ei, ew, E);
    k_enc <<<(N + 127) / 128, 128>>>(x, encW, encb, N);
    k_l1  <<<(N + 15) / 16, 256>>>(N);
    k_l2  <<<(N + NPB - 1) / NPB, 256>>>(W1, b1, W2, b2, c1W, c1b, c2W, c2b, out, N);
}